// round 1
// baseline (speedup 1.0000x reference)
#include <cuda_runtime.h>

#define NTARGET 50000
#define NDRUG   50000
#define NEDGE   800000
#define FDIM    128
#define CDIM    64
#define NEG_SLOPE 0.2f

// ---------------- scratch (static device globals; no allocation) -----------
__device__ float g_H[4][(size_t)50000 * 64];   // 0=tt_src,1=dt_src,2=dd_src,3=td_src
__device__ float g_alpha[8][50000];            // per-relation src/dst attention scalars
__device__ float g_v[8][128];                  // W @ att vectors
__device__ int2  g_edges[4][NEDGE];            // sorted {src, logit-bits}
__device__ int   g_cnt[4][50000];
__device__ int   g_cur[4][50000];
__device__ int   g_off[4][50001];

// ---------------- utility kernels ------------------------------------------
__global__ void zero_kernel() {
    int i = blockIdx.x * blockDim.x + threadIdx.x;
    if (i < 4 * 50000) {
        ((int*)g_cnt)[i] = 0;
        ((int*)g_cur)[i] = 0;
    }
}

__global__ void hist_kernel(const int* __restrict__ dst, int rel) {
    int i = blockIdx.x * blockDim.x + threadIdx.x;
    if (i < NEDGE) atomicAdd(&g_cnt[rel][dst[i]], 1);
}

// one block per relation, 1024 threads, chunked block scan
__global__ void scan_kernel() {
    int r = blockIdx.x;
    const int* cnt = g_cnt[r];
    int* off = g_off[r];
    const int n = 50000;
    __shared__ int wsum[32];
    __shared__ int carry;
    int tid = threadIdx.x, lane = tid & 31, wid = tid >> 5;
    if (tid == 0) { carry = 0; off[0] = 0; }
    __syncthreads();
    for (int base = 0; base < n; base += 1024) {
        int idx = base + tid;
        int v = (idx < n) ? cnt[idx] : 0;
        int x = v;
        #pragma unroll
        for (int d = 1; d < 32; d <<= 1) {
            int y = __shfl_up_sync(0xffffffffu, x, d);
            if (lane >= d) x += y;
        }
        if (lane == 31) wsum[wid] = x;
        __syncthreads();
        if (wid == 0) {
            int s = wsum[lane];
            #pragma unroll
            for (int d = 1; d < 32; d <<= 1) {
                int y = __shfl_up_sync(0xffffffffu, s, d);
                if (lane >= d) s += y;
            }
            wsum[lane] = s;
        }
        __syncthreads();
        int woff = wid ? wsum[wid - 1] : 0;
        int incl = x + woff + carry;
        if (idx < n) off[idx + 1] = incl;
        int total = wsum[31];
        __syncthreads();
        if (tid == 0) carry += total;
        __syncthreads();
    }
}

// v_j = W_j @ a_j  (8 pairs, one block each)
__global__ void vcomp_kernel(
    const float* W_tt, const float* W_dts, const float* W_dtd,
    const float* W_dd, const float* W_tds, const float* W_tdd,
    const float* a_tts, const float* a_ttd, const float* a_dts, const float* a_dtd,
    const float* a_dds, const float* a_ddd, const float* a_tds, const float* a_tdd)
{
    int j = blockIdx.x;
    const float* W = nullptr; const float* a = nullptr; int K = 128;
    switch (j) {
        case 0: W = W_tt;  a = a_tts; break;
        case 1: W = W_tt;  a = a_ttd; break;
        case 2: W = W_dts; a = a_dts; break;
        case 3: W = W_dtd; a = a_dtd; break;
        case 4: W = W_dd;  a = a_dds; break;
        case 5: W = W_dd;  a = a_ddd; break;
        case 6: W = W_tds; a = a_tds; K = 64; break;
        case 7: W = W_tdd; a = a_tdd; break;
    }
    int k = threadIdx.x;
    if (k < K) {
        float s = 0.f;
        #pragma unroll
        for (int c = 0; c < 64; c++) s += W[k * 64 + c] * a[c];
        g_v[j][k] = s;
    }
}

// alpha[ai][row] = X[row,:] . g_v[vi]   (warp per row, up to 4 vectors)
__global__ void alpha_kernel(const float* __restrict__ X, int N, int K,
                             int vi0, int ai0, int vi1, int ai1,
                             int vi2, int ai2, int vi3, int ai3, int nv)
{
    int warp = (blockIdx.x * blockDim.x + threadIdx.x) >> 5;
    int lane = threadIdx.x & 31;
    if (warp >= N) return;
    const float* xr = X + (size_t)warp * K;
    int nt = K >> 5;
    float xv[4];
    #pragma unroll
    for (int t = 0; t < 4; t++) xv[t] = (t < nt) ? xr[lane + 32 * t] : 0.f;
    int vis[4] = {vi0, vi1, vi2, vi3};
    int ais[4] = {ai0, ai1, ai2, ai3};
    for (int j = 0; j < nv; j++) {
        const float* v = g_v[vis[j]];
        float p = 0.f;
        #pragma unroll
        for (int t = 0; t < 4; t++) if (t < nt) p += xv[t] * v[lane + 32 * t];
        #pragma unroll
        for (int d = 16; d; d >>= 1) p += __shfl_xor_sync(0xffffffffu, p, d);
        if (lane == 0) g_alpha[ais[j]][warp] = p;
    }
}

// ---------------- GEMM: H = X[N,K] @ W[K,64] --------------------------------
template <int K>
__global__ __launch_bounds__(256) void gemm_kernel(
    const float* __restrict__ X, const float* __restrict__ W, int outIdx, int N)
{
    __shared__ float Ws[K * 64];
    __shared__ float Xs[16 * K];
    float* Hout = g_H[outIdx];
    for (int i = threadIdx.x; i < K * 64; i += 256) Ws[i] = W[i];
    int c  = threadIdx.x & 63;
    int rs = threadIdx.x >> 6;          // 0..3, uniform within each warp
    int ntiles = (N + 15) / 16;
    for (int tile = blockIdx.x; tile < ntiles; tile += gridDim.x) {
        int row0 = tile * 16;
        __syncthreads();
        for (int i = threadIdx.x; i < 16 * K; i += 256) {
            int r = i / K, k = i - r * K;
            int gr = row0 + r;
            Xs[i] = (gr < N) ? X[(size_t)gr * K + k] : 0.f;
        }
        __syncthreads();
        float acc[4] = {0.f, 0.f, 0.f, 0.f};
        #pragma unroll 4
        for (int k = 0; k < K; k++) {
            float w = Ws[k * 64 + c];
            #pragma unroll
            for (int i = 0; i < 4; i++)
                acc[i] += Xs[(rs * 4 + i) * K + k] * w;
        }
        #pragma unroll
        for (int i = 0; i < 4; i++) {
            int gr = row0 + rs * 4 + i;
            if (gr < N) Hout[(size_t)gr * 64 + c] = acc[i];
        }
    }
}

// ---------------- edge scatter (counting-sort payload) ----------------------
__global__ void scatter_kernel(const int* __restrict__ src, const int* __restrict__ dst,
                               int rel, int asIdx, int adIdx)
{
    int i = blockIdx.x * blockDim.x + threadIdx.x;
    if (i >= NEDGE) return;
    int s = src[i], d = dst[i];
    float l = g_alpha[asIdx][s] + g_alpha[adIdx][d];
    l = (l > 0.f) ? l : NEG_SLOPE * l;
    int pos = g_off[rel][d] + atomicAdd(&g_cur[rel][d], 1);
    g_edges[rel][pos] = make_int2(s, __float_as_int(l));
}

// ---------------- per-dst-node softmax aggregation (warp per node) ----------
__global__ __launch_bounds__(256) void agg_kernel(int rel, int hIdx,
                                                  const float* __restrict__ bias,
                                                  float* __restrict__ out,
                                                  int n, int combine)
{
    int warp = (blockIdx.x * blockDim.x + threadIdx.x) >> 5;
    int lane = threadIdx.x & 31;
    if (warp >= n) return;
    const int* off = g_off[rel];
    const int2* edges = g_edges[rel];
    const float* H = g_H[hIdx];
    int s = off[warp], e = off[warp + 1];

    float m = -3.4e38f;
    for (int i = s + lane; i < e; i += 32)
        m = fmaxf(m, __int_as_float(edges[i].y));
    #pragma unroll
    for (int d = 16; d; d >>= 1) m = fmaxf(m, __shfl_xor_sync(0xffffffffu, m, d));

    float den = 0.f;
    for (int i = s + lane; i < e; i += 32)
        den += __expf(__int_as_float(edges[i].y) - m);
    #pragma unroll
    for (int d = 16; d; d >>= 1) den += __shfl_xor_sync(0xffffffffu, den, d);

    float a0 = 0.f, a1 = 0.f;
    for (int i = s; i < e; i++) {
        int2 ed = edges[i];                       // broadcast load
        float w = __expf(__int_as_float(ed.y) - m);
        const float* hr = H + (size_t)ed.x * 64;  // coalesced 2x128B
        a0 += w * hr[lane];
        a1 += w * hr[lane + 32];
    }
    float inv = 1.f / (den + 1e-16f);
    float o0 = a0 * inv + bias[lane];
    float o1 = a1 * inv + bias[lane + 32];
    float* orow = out + (size_t)warp * 64;
    if (combine) {
        o0 = 0.5f * (orow[lane] + o0);
        o1 = 0.5f * (orow[lane + 32] + o1);
    }
    orow[lane] = o0;
    orow[lane + 32] = o1;
}

// ---------------- launch ----------------------------------------------------
extern "C" void kernel_launch(void* const* d_in, const int* in_sizes, int n_in,
                              void* d_out, int out_size)
{
    const float* x_target   = (const float*)d_in[0];
    const float* x_drug     = (const float*)d_in[1];
    const int*   ei_tt      = (const int*)d_in[2];
    const int*   ei_dt      = (const int*)d_in[3];
    const int*   ei_dd      = (const int*)d_in[4];
    const int*   ei_td      = (const int*)d_in[5];
    const float* W_tt       = (const float*)d_in[6];
    const float* att_tt_src = (const float*)d_in[7];
    const float* att_tt_dst = (const float*)d_in[8];
    const float* b_tt       = (const float*)d_in[9];
    const float* W_dt_src   = (const float*)d_in[10];
    const float* W_dt_dst   = (const float*)d_in[11];
    const float* att_dt_src = (const float*)d_in[12];
    const float* att_dt_dst = (const float*)d_in[13];
    const float* b_dt       = (const float*)d_in[14];
    const float* W_dd       = (const float*)d_in[15];
    const float* att_dd_src = (const float*)d_in[16];
    const float* att_dd_dst = (const float*)d_in[17];
    const float* b_dd       = (const float*)d_in[18];
    const float* W_td_src   = (const float*)d_in[19];
    const float* W_td_dst   = (const float*)d_in[20];
    const float* att_td_src = (const float*)d_in[21];
    const float* att_td_dst = (const float*)d_in[22];
    const float* b_td       = (const float*)d_in[23];

    float* out_t = (float*)d_out;                       // x_target_new [50000,64]
    float* out_d = out_t + (size_t)NTARGET * CDIM;      // x_drug_new  [50000,64]

    const int EB = (NEDGE + 255) / 256;                 // 3125
    const int WB = (NTARGET * 32 + 255) / 256;          // 6250 (warp per node)
    const int GB = (NTARGET + 15) / 16;                 // 3125 gemm tiles

    // CSR build (feature-independent)
    zero_kernel<<<(4 * 50000 + 255) / 256, 256>>>();
    hist_kernel<<<EB, 256>>>(ei_tt + NEDGE, 0);
    hist_kernel<<<EB, 256>>>(ei_dt + NEDGE, 1);
    hist_kernel<<<EB, 256>>>(ei_dd + NEDGE, 2);
    hist_kernel<<<EB, 256>>>(ei_td + NEDGE, 3);
    scan_kernel<<<4, 1024>>>();

    // attention vectors + alphas + src-feature GEMMs
    vcomp_kernel<<<8, 128>>>(W_tt, W_dt_src, W_dt_dst, W_dd, W_td_src, W_td_dst,
                             att_tt_src, att_tt_dst, att_dt_src, att_dt_dst,
                             att_dd_src, att_dd_dst, att_td_src, att_td_dst);
    // target alphas: a0=tt_src, a1=tt_dst, a3=dt_dst
    alpha_kernel<<<WB, 256>>>(x_target, NTARGET, 128, 0, 0, 1, 1, 3, 3, 0, 0, 3);
    // drug alphas: a2=dt_src, a4=dd_src, a5=dd_dst, a7=td_dst
    alpha_kernel<<<WB, 256>>>(x_drug, NDRUG, 128, 2, 2, 4, 4, 5, 5, 7, 7, 4);

    gemm_kernel<128><<<GB, 256>>>(x_target, W_tt,     0, NTARGET);
    gemm_kernel<128><<<GB, 256>>>(x_drug,   W_dt_src, 1, NDRUG);
    gemm_kernel<128><<<GB, 256>>>(x_drug,   W_dd,     2, NDRUG);

    // logits + bucket scatter for the 3 feature-ready relations
    scatter_kernel<<<EB, 256>>>(ei_tt, ei_tt + NEDGE, 0, 0, 1);
    scatter_kernel<<<EB, 256>>>(ei_dt, ei_dt + NEDGE, 1, 2, 3);
    scatter_kernel<<<EB, 256>>>(ei_dd, ei_dd + NEDGE, 2, 4, 5);

    // x_target_new = 0.5*(gat_tt + gat_dt)
    agg_kernel<<<WB, 256>>>(0, 0, b_tt, out_t, NTARGET, 0);
    agg_kernel<<<WB, 256>>>(1, 1, b_dt, out_t, NTARGET, 1);

    // td relation depends on x_target_new
    gemm_kernel<64><<<GB, 256>>>(out_t, W_td_src, 3, NTARGET);
    alpha_kernel<<<WB, 256>>>(out_t, NTARGET, 64, 6, 6, 0, 0, 0, 0, 0, 0, 1);
    scatter_kernel<<<EB, 256>>>(ei_td, ei_td + NEDGE, 3, 6, 7);

    // x_drug_new = 0.5*(gat_dd + gat_td)
    agg_kernel<<<WB, 256>>>(2, 2, b_dd, out_d, NDRUG, 0);
    agg_kernel<<<WB, 256>>>(3, 3, b_td, out_d, NDRUG, 1);
}

// round 2
// speedup vs baseline: 1.4101x; 1.4101x over previous
#include <cuda_runtime.h>

#define NTARGET 50000
#define NDRUG   50000
#define NEDGE   800000
#define FDIM    128
#define CDIM    64
#define NEG_SLOPE 0.2f
#define NB      196          // ceil(50000/256)

// ---------------- scratch (static device globals; no allocation) -----------
__device__ float g_H[4][(size_t)50000 * 64];   // 0=tt_src,1=dt_src,2=dd_src,3=td_src
__device__ float g_alpha[8][50000];            // per-relation src/dst attention scalars
__device__ float g_v[8][128];                  // W @ att vectors
__device__ int2  g_edges[4][NEDGE];            // bucketed {src, logit-bits}
__device__ int   g_cnt[4][50000];
__device__ int   g_cur[4][50000];
__device__ int   g_off[4][50001];
__device__ int   g_bsum[4][NB];
__device__ int   g_boff[4][NB];

// ---------------- utility kernels ------------------------------------------
__global__ void zero_kernel() {
    int i = blockIdx.x * blockDim.x + threadIdx.x;
    if (i < 4 * 50000) {
        ((int*)g_cnt)[i] = 0;
        ((int*)g_cur)[i] = 0;
    }
}

__global__ void hist4_kernel(const int* __restrict__ d0, const int* __restrict__ d1,
                             const int* __restrict__ d2, const int* __restrict__ d3) {
    int i = blockIdx.x * blockDim.x + threadIdx.x;
    int rel = blockIdx.y;
    const int* d = (rel == 0) ? d0 : (rel == 1) ? d1 : (rel == 2) ? d2 : d3;
    if (i < NEDGE) atomicAdd(&g_cnt[rel][d[i]], 1);
}

// ---------------- 3-phase scan ----------------------------------------------
__global__ void bsum_kernel() {
    int rel = blockIdx.y;
    int idx = blockIdx.x * 256 + threadIdx.x;
    int v = (idx < 50000) ? g_cnt[rel][idx] : 0;
    #pragma unroll
    for (int d = 16; d; d >>= 1) v += __shfl_xor_sync(0xffffffffu, v, d);
    __shared__ int s[8];
    int lane = threadIdx.x & 31, wid = threadIdx.x >> 5;
    if (lane == 0) s[wid] = v;
    __syncthreads();
    if (threadIdx.x == 0) {
        int t = 0;
        #pragma unroll
        for (int i = 0; i < 8; i++) t += s[i];
        g_bsum[rel][blockIdx.x] = t;
    }
}

__global__ void bscan_kernel() {   // 1 block, 256 threads
    __shared__ int wsum[8];
    int tid = threadIdx.x, lane = tid & 31, wid = tid >> 5;
    for (int rel = 0; rel < 4; rel++) {
        int v = (tid < NB) ? g_bsum[rel][tid] : 0;
        int x = v;
        #pragma unroll
        for (int d = 1; d < 32; d <<= 1) {
            int y = __shfl_up_sync(0xffffffffu, x, d);
            if (lane >= d) x += y;
        }
        if (lane == 31) wsum[wid] = x;
        __syncthreads();
        if (wid == 0) {
            int sv = (lane < 8) ? wsum[lane] : 0;
            #pragma unroll
            for (int d = 1; d < 8; d <<= 1) {
                int y = __shfl_up_sync(0xffffffffu, sv, d);
                if (lane >= d) sv += y;
            }
            if (lane < 8) wsum[lane] = sv;
        }
        __syncthreads();
        int incl = x + (wid ? wsum[wid - 1] : 0);
        if (tid < NB) g_boff[rel][tid] = incl - v;   // exclusive prefix
        __syncthreads();
    }
}

__global__ void off_kernel() {
    int rel = blockIdx.y;
    int idx = blockIdx.x * 256 + threadIdx.x;
    int v = (idx < 50000) ? g_cnt[rel][idx] : 0;
    __shared__ int wsum[8];
    int lane = threadIdx.x & 31, wid = threadIdx.x >> 5;
    int x = v;
    #pragma unroll
    for (int d = 1; d < 32; d <<= 1) {
        int y = __shfl_up_sync(0xffffffffu, x, d);
        if (lane >= d) x += y;
    }
    if (lane == 31) wsum[wid] = x;
    __syncthreads();
    if (wid == 0) {
        int sv = (lane < 8) ? wsum[lane] : 0;
        #pragma unroll
        for (int d = 1; d < 8; d <<= 1) {
            int y = __shfl_up_sync(0xffffffffu, sv, d);
            if (lane >= d) sv += y;
        }
        if (lane < 8) wsum[lane] = sv;
    }
    __syncthreads();
    int incl = x + (wid ? wsum[wid - 1] : 0) + g_boff[rel][blockIdx.x];
    if (idx < 50000) g_off[rel][idx + 1] = incl;
    if (idx == 0) g_off[rel][0] = 0;
}

// ---------------- v_j = W_j @ a_j -------------------------------------------
__global__ void vcomp_kernel(
    const float* W_tt, const float* W_dts, const float* W_dtd,
    const float* W_dd, const float* W_tds, const float* W_tdd,
    const float* a_tts, const float* a_ttd, const float* a_dts, const float* a_dtd,
    const float* a_dds, const float* a_ddd, const float* a_tds, const float* a_tdd)
{
    int j = blockIdx.x;
    const float* W = nullptr; const float* a = nullptr; int K = 128;
    switch (j) {
        case 0: W = W_tt;  a = a_tts; break;
        case 1: W = W_tt;  a = a_ttd; break;
        case 2: W = W_dts; a = a_dts; break;
        case 3: W = W_dtd; a = a_dtd; break;
        case 4: W = W_dd;  a = a_dds; break;
        case 5: W = W_dd;  a = a_ddd; break;
        case 6: W = W_tds; a = a_tds; K = 64; break;
        case 7: W = W_tdd; a = a_tdd; break;
    }
    int k = threadIdx.x;
    if (k < K) {
        float s = 0.f;
        #pragma unroll
        for (int c = 0; c < 64; c++) s += W[k * 64 + c] * a[c];
        g_v[j][k] = s;
    }
}

// alpha[ai][row] = X[row,:] . g_v[vi]   (warp per row, up to 4 vectors)
__global__ void alpha_kernel(const float* __restrict__ X, int N, int K,
                             int vi0, int ai0, int vi1, int ai1,
                             int vi2, int ai2, int vi3, int ai3, int nv)
{
    int warp = (blockIdx.x * blockDim.x + threadIdx.x) >> 5;
    int lane = threadIdx.x & 31;
    if (warp >= N) return;
    const float* xr = X + (size_t)warp * K;
    int nt = K >> 5;
    float xv[4];
    #pragma unroll
    for (int t = 0; t < 4; t++) xv[t] = (t < nt) ? xr[lane + 32 * t] : 0.f;
    int vis[4] = {vi0, vi1, vi2, vi3};
    int ais[4] = {ai0, ai1, ai2, ai3};
    for (int j = 0; j < nv; j++) {
        const float* v = g_v[vis[j]];
        float p = 0.f;
        #pragma unroll
        for (int t = 0; t < 4; t++) if (t < nt) p += xv[t] * v[lane + 32 * t];
        #pragma unroll
        for (int d = 16; d; d >>= 1) p += __shfl_xor_sync(0xffffffffu, p, d);
        if (lane == 0) g_alpha[ais[j]][warp] = p;
    }
}

// ---------------- GEMM: H = X[N,K] @ W[K,64], 128x64 tile, 8x4 microtile ----
template <int K>
__global__ __launch_bounds__(256) void gemm_kernel(
    const float* __restrict__ X, const float* __restrict__ W, int outIdx, int N)
{
    __shared__ float Xt[16][132];   // k-major transposed X chunk
    __shared__ float Ws[16][64];
    float* __restrict__ Hout = g_H[outIdx];
    const int tid = threadIdx.x;
    const int tc = tid & 15;        // cols tc*4 .. +3
    const int tr = tid >> 4;        // rows tr*8 .. +7
    const int row0 = blockIdx.x * 128;

    // global-load mapping: X chunk 128x16 = 512 float4 (2/thread), W 16x64 = 256 float4
    const int f0 = tid * 2;
    const int xrow0 = f0 >> 2, xkq0 = (f0 & 3) * 4;
    const int xrow1 = (f0 + 1) >> 2, xkq1 = ((f0 + 1) & 3) * 4;
    const int wrow = tid >> 4;
    const int wc4 = (tid & 15) * 4;

    const float4 zf4 = make_float4(0.f, 0.f, 0.f, 0.f);
    float4 xg0, xg1, wg;
    {
        int gr0 = row0 + xrow0, gr1 = row0 + xrow1;
        xg0 = (gr0 < N) ? *(const float4*)(X + (size_t)gr0 * K + xkq0) : zf4;
        xg1 = (gr1 < N) ? *(const float4*)(X + (size_t)gr1 * K + xkq1) : zf4;
        wg  = *(const float4*)(W + (size_t)wrow * 64 + wc4);
    }

    float acc[8][4];
    #pragma unroll
    for (int i = 0; i < 8; i++)
        #pragma unroll
        for (int j = 0; j < 4; j++) acc[i][j] = 0.f;

    #pragma unroll 1
    for (int kc = 0; kc < K; kc += 16) {
        Xt[xkq0 + 0][xrow0] = xg0.x; Xt[xkq0 + 1][xrow0] = xg0.y;
        Xt[xkq0 + 2][xrow0] = xg0.z; Xt[xkq0 + 3][xrow0] = xg0.w;
        Xt[xkq1 + 0][xrow1] = xg1.x; Xt[xkq1 + 1][xrow1] = xg1.y;
        Xt[xkq1 + 2][xrow1] = xg1.z; Xt[xkq1 + 3][xrow1] = xg1.w;
        *(float4*)&Ws[wrow][wc4] = wg;
        __syncthreads();
        if (kc + 16 < K) {
            int kn = kc + 16;
            int gr0 = row0 + xrow0, gr1 = row0 + xrow1;
            xg0 = (gr0 < N) ? *(const float4*)(X + (size_t)gr0 * K + kn + xkq0) : zf4;
            xg1 = (gr1 < N) ? *(const float4*)(X + (size_t)gr1 * K + kn + xkq1) : zf4;
            wg  = *(const float4*)(W + (size_t)(kn + wrow) * 64 + wc4);
        }
        #pragma unroll
        for (int k = 0; k < 16; k++) {
            float4 x0 = *(const float4*)&Xt[k][tr * 8];
            float4 x1 = *(const float4*)&Xt[k][tr * 8 + 4];
            float4 wv = *(const float4*)&Ws[k][tc * 4];
            float xs[8] = {x0.x, x0.y, x0.z, x0.w, x1.x, x1.y, x1.z, x1.w};
            float wf[4] = {wv.x, wv.y, wv.z, wv.w};
            #pragma unroll
            for (int i = 0; i < 8; i++)
                #pragma unroll
                for (int j = 0; j < 4; j++)
                    acc[i][j] += xs[i] * wf[j];
        }
        __syncthreads();
    }
    #pragma unroll
    for (int i = 0; i < 8; i++) {
        int gr = row0 + tr * 8 + i;
        if (gr < N)
            *(float4*)(Hout + (size_t)gr * 64 + tc * 4) =
                make_float4(acc[i][0], acc[i][1], acc[i][2], acc[i][3]);
    }
}

// ---------------- edge scatter (counting-sort payload) ----------------------
__global__ void scatter_kernel(const int* __restrict__ src, const int* __restrict__ dst,
                               int rel, int asIdx, int adIdx)
{
    int i = blockIdx.x * blockDim.x + threadIdx.x;
    if (i >= NEDGE) return;
    int s = src[i], d = dst[i];
    float l = g_alpha[asIdx][s] + g_alpha[adIdx][d];
    l = (l > 0.f) ? l : NEG_SLOPE * l;
    int pos = g_off[rel][d] + atomicAdd(&g_cur[rel][d], 1);
    g_edges[rel][pos] = make_int2(s, __float_as_int(l));
}

// ---------------- per-node GAT aggregation (no max pass, unrolled) ----------
__device__ __forceinline__ void gat_node(int rel, int hIdx, int node, int lane,
                                         float& o0, float& o1)
{
    const int* __restrict__ off = g_off[rel];
    const int2* __restrict__ edges = g_edges[rel];
    const float* __restrict__ H = g_H[hIdx];
    int s = off[node], e = off[node + 1];

    float den = 0.f;
    for (int i = s + lane; i < e; i += 32)
        den += __expf(__int_as_float(edges[i].y));
    #pragma unroll
    for (int d = 16; d; d >>= 1) den += __shfl_xor_sync(0xffffffffu, den, d);

    float a0 = 0.f, a1 = 0.f;
    int i = s;
    for (; i + 2 <= e; i += 2) {
        int2 e0 = edges[i], e1 = edges[i + 1];
        float w0 = __expf(__int_as_float(e0.y));
        float w1 = __expf(__int_as_float(e1.y));
        const float* h0 = H + (size_t)e0.x * 64;
        const float* h1 = H + (size_t)e1.x * 64;
        a0 += w0 * h0[lane];      a1 += w0 * h0[lane + 32];
        a0 += w1 * h1[lane];      a1 += w1 * h1[lane + 32];
    }
    if (i < e) {
        int2 e0 = edges[i];
        float w0 = __expf(__int_as_float(e0.y));
        const float* h0 = H + (size_t)e0.x * 64;
        a0 += w0 * h0[lane];      a1 += w0 * h0[lane + 32];
    }
    float inv = 1.f / (den + 1e-16f);
    o0 = a0 * inv;
    o1 = a1 * inv;
}

// out = 0.5*((gatA + bA) + (gatB + bB)), warp per node
__global__ __launch_bounds__(256) void agg2_kernel(
    int relA, int hA, const float* __restrict__ bA,
    int relB, int hB, const float* __restrict__ bB,
    float* __restrict__ out, int n)
{
    int warp = (blockIdx.x * blockDim.x + threadIdx.x) >> 5;
    int lane = threadIdx.x & 31;
    if (warp >= n) return;
    float a0, a1, c0, c1;
    gat_node(relA, hA, warp, lane, a0, a1);
    gat_node(relB, hB, warp, lane, c0, c1);
    float o0 = 0.5f * (a0 + bA[lane]      + c0 + bB[lane]);
    float o1 = 0.5f * (a1 + bA[lane + 32] + c1 + bB[lane + 32]);
    float* orow = out + (size_t)warp * 64;
    orow[lane] = o0;
    orow[lane + 32] = o1;
}

// ---------------- launch ----------------------------------------------------
extern "C" void kernel_launch(void* const* d_in, const int* in_sizes, int n_in,
                              void* d_out, int out_size)
{
    const float* x_target   = (const float*)d_in[0];
    const float* x_drug     = (const float*)d_in[1];
    const int*   ei_tt      = (const int*)d_in[2];
    const int*   ei_dt      = (const int*)d_in[3];
    const int*   ei_dd      = (const int*)d_in[4];
    const int*   ei_td      = (const int*)d_in[5];
    const float* W_tt       = (const float*)d_in[6];
    const float* att_tt_src = (const float*)d_in[7];
    const float* att_tt_dst = (const float*)d_in[8];
    const float* b_tt       = (const float*)d_in[9];
    const float* W_dt_src   = (const float*)d_in[10];
    const float* W_dt_dst   = (const float*)d_in[11];
    const float* att_dt_src = (const float*)d_in[12];
    const float* att_dt_dst = (const float*)d_in[13];
    const float* b_dt       = (const float*)d_in[14];
    const float* W_dd       = (const float*)d_in[15];
    const float* att_dd_src = (const float*)d_in[16];
    const float* att_dd_dst = (const float*)d_in[17];
    const float* b_dd       = (const float*)d_in[18];
    const float* W_td_src   = (const float*)d_in[19];
    const float* W_td_dst   = (const float*)d_in[20];
    const float* att_td_src = (const float*)d_in[21];
    const float* att_td_dst = (const float*)d_in[22];
    const float* b_td       = (const float*)d_in[23];

    float* out_t = (float*)d_out;                       // x_target_new [50000,64]
    float* out_d = out_t + (size_t)NTARGET * CDIM;      // x_drug_new  [50000,64]

    const int EB = (NEDGE + 255) / 256;                 // 3125
    const int WB = (NTARGET * 32 + 255) / 256;          // 6250 (warp per node)
    const int GB = (NTARGET + 127) / 128;               // 391 gemm tiles

    // CSR build (feature-independent)
    zero_kernel<<<(4 * 50000 + 255) / 256, 256>>>();
    hist4_kernel<<<dim3(EB, 4), 256>>>(ei_tt + NEDGE, ei_dt + NEDGE,
                                       ei_dd + NEDGE, ei_td + NEDGE);
    bsum_kernel<<<dim3(NB, 4), 256>>>();
    bscan_kernel<<<1, 256>>>();
    off_kernel<<<dim3(NB, 4), 256>>>();

    // attention vectors + alphas + src-feature GEMMs
    vcomp_kernel<<<8, 128>>>(W_tt, W_dt_src, W_dt_dst, W_dd, W_td_src, W_td_dst,
                             att_tt_src, att_tt_dst, att_dt_src, att_dt_dst,
                             att_dd_src, att_dd_dst, att_td_src, att_td_dst);
    alpha_kernel<<<WB, 256>>>(x_target, NTARGET, 128, 0, 0, 1, 1, 3, 3, 0, 0, 3);
    alpha_kernel<<<WB, 256>>>(x_drug, NDRUG, 128, 2, 2, 4, 4, 5, 5, 7, 7, 4);

    gemm_kernel<128><<<GB, 256>>>(x_target, W_tt,     0, NTARGET);
    gemm_kernel<128><<<GB, 256>>>(x_drug,   W_dt_src, 1, NDRUG);
    gemm_kernel<128><<<GB, 256>>>(x_drug,   W_dd,     2, NDRUG);

    scatter_kernel<<<EB, 256>>>(ei_tt, ei_tt + NEDGE, 0, 0, 1);
    scatter_kernel<<<EB, 256>>>(ei_dt, ei_dt + NEDGE, 1, 2, 3);
    scatter_kernel<<<EB, 256>>>(ei_dd, ei_dd + NEDGE, 2, 4, 5);

    // x_target_new = 0.5*(gat_tt + gat_dt)
    agg2_kernel<<<WB, 256>>>(0, 0, b_tt, 1, 1, b_dt, out_t, NTARGET);

    // td relation depends on x_target_new
    gemm_kernel<64><<<GB, 256>>>(out_t, W_td_src, 3, NTARGET);
    alpha_kernel<<<WB, 256>>>(out_t, NTARGET, 64, 6, 6, 0, 0, 0, 0, 0, 0, 1);
    scatter_kernel<<<EB, 256>>>(ei_td, ei_td + NEDGE, 3, 6, 7);

    // x_drug_new = 0.5*(gat_dd + gat_td)
    agg2_kernel<<<WB, 256>>>(2, 2, b_dd, 3, 3, b_td, out_d, NDRUG);
}